// round 2
// baseline (speedup 1.0000x reference)
#include <cuda_runtime.h>
#include <math.h>

#define SK        131072
#define S_SUB     16384
#define E_CNT     196608
#define H         128
#define N_TOT     4096
#define M_SUB     4
#define K_SUB     8
#define L_LAYERS  4
#define NUM_G     32

typedef unsigned long long ull;

// ---------------- scratch (static device memory; no allocations) ----------------
__device__ float g_h[SK * H];     // node features (64 MB)
__device__ float g_aggr[SK * H];  // message aggregation buffer (64 MB)

// ---------------- packed f32x2 helpers (Blackwell FFMA2 path) ----------------
__device__ __forceinline__ ull pk2(float a) {
    ull r; asm("mov.b64 %0, {%1, %1};" : "=l"(r) : "f"(a)); return r;
}
__device__ __forceinline__ void fma2(ull& d, ull a, ull b) {
    asm("fma.rn.f32x2 %0, %1, %2, %0;" : "+l"(d) : "l"(a), "l"(b));
}
__device__ __forceinline__ float2 upk(ull p) {
    float2 f; asm("mov.b64 {%0, %1}, %2;" : "=f"(f.x), "=f"(f.y) : "l"(p)); return f;
}

// ---------------- kernels ----------------

__global__ void zero_aggr_kernel() {
    int i = blockIdx.x * blockDim.x + threadIdx.x;   // SK*H/4 threads
    ((float4*)g_aggr)[i] = make_float4(0.f, 0.f, 0.f, 0.f);
}

__global__ void embed_kernel(const int* __restrict__ x_tokens,
                             const int* __restrict__ node_ids,
                             const float* __restrict__ atom_emb,
                             const float* __restrict__ role_emb) {
    int t = blockIdx.x * blockDim.x + threadIdx.x;   // SK*32 threads (warp per node)
    int node = t >> 5;
    int lane = t & 31;
    int tok = x_tokens[node];
    float vf = (node_ids[node] >= 0) ? 1.0f : 0.0f;
    int is_root = ((node & (K_SUB - 1)) == 0) ? 1 : 0;
    int c = lane * 4;
    float4 a = *(const float4*)(&atom_emb[tok * H + c]);
    float4 r = *(const float4*)(&role_emb[is_root * H + c]);
    float4 o;
    o.x = (a.x + r.x) * vf;
    o.y = (a.y + r.y) * vf;
    o.z = (a.z + r.z) * vf;
    o.w = (a.w + r.w) * vf;
    *(float4*)(&g_h[node * H + c]) = o;
}

__global__ void edge_kernel(const int* __restrict__ src,
                            const int* __restrict__ dst,
                            const int* __restrict__ etok,
                            const float* __restrict__ bond_emb) {
    int t = blockIdx.x * blockDim.x + threadIdx.x;   // E*32 threads (warp per edge)
    int e = t >> 5;
    if (e >= E_CNT) return;
    int lane = t & 31;
    int s  = src[e];
    int d  = dst[e];
    int bt = etok[e];
    int c = lane * 4;
    float4 hv = *(const float4*)(&g_h[s * H + c]);
    float4 bv = *(const float4*)(&bond_emb[bt * H + c]);
    float4 m;
    m.x = fmaxf(hv.x + bv.x, 0.f);
    m.y = fmaxf(hv.y + bv.y, 0.f);
    m.z = fmaxf(hv.z + bv.z, 0.f);
    m.w = fmaxf(hv.w + bv.w, 0.f);
    float* zp = &g_aggr[d * H + c];
    atomicAdd(zp + 0, m.x);
    atomicAdd(zp + 1, m.y);
    atomicAdd(zp + 2, m.z);
    atomicAdd(zp + 3, m.w);
}

// Fused 2-GEMM MLP with packed f32x2 FMAs:
//   h <- ( relu( ((1+eps)h + aggr) @ W1 + b1 ) @ W2 + b2 ) * vf
// Block: 256 threads, tile 64 rows x 128 cols.
// Thread (tx=tid&7, ty=tid>>3): rows {ty, ty+32}, cols {4*tx+32*j | j=0..3}.
// Accumulators: packed f32x2 column-pairs (FFMA2).
#define MLP_ROWS  64
#define ZS_STRIDE 132
#define MLP_SMEM_FLOATS (MLP_ROWS * ZS_STRIDE + H * H + H)
#define MLP_SMEM_BYTES  (MLP_SMEM_FLOATS * 4)

__global__ __launch_bounds__(256, 2)
void mlp_kernel(const float* __restrict__ W1, const float* __restrict__ b1,
                const float* __restrict__ W2, const float* __restrict__ b2,
                const float* __restrict__ eps, int l, int zero_next,
                const int* __restrict__ node_ids) {
    extern __shared__ float smem[];
    float* zs = smem;                          // [64][132]
    float* ws = smem + MLP_ROWS * ZS_STRIDE;   // [128][128]
    float* bs = ws + H * H;                    // [128]

    const int tid  = threadIdx.x;
    const int tx   = tid & 7;
    const int ty   = tid >> 3;
    const int row0 = blockIdx.x * MLP_ROWS;
    const float epsl = 1.0f + eps[l];

    // ---- stage input tile: zs = (1+eps)*h + aggr  (and zero aggr for next layer)
#pragma unroll
    for (int i = 0; i < 8; i++) {
        int idx = tid + i * 256;               // 2048 float4s
        int r = idx >> 5;
        int c = (idx & 31) << 2;
        float4 hv = *(const float4*)(&g_h[(row0 + r) * H + c]);
        float4 av = *(const float4*)(&g_aggr[(row0 + r) * H + c]);
        float4 z;
        z.x = epsl * hv.x + av.x;
        z.y = epsl * hv.y + av.y;
        z.z = epsl * hv.z + av.z;
        z.w = epsl * hv.w + av.w;
        *(float4*)(&zs[r * ZS_STRIDE + c]) = z;
        if (zero_next)
            *(float4*)(&g_aggr[(row0 + r) * H + c]) = make_float4(0.f, 0.f, 0.f, 0.f);
    }
#pragma unroll
    for (int i = 0; i < 16; i++)
        ((float4*)ws)[tid + i * 256] = ((const float4*)W1)[tid + i * 256];
    if (tid < 32) ((float4*)bs)[tid] = ((const float4*)b1)[tid];
    __syncthreads();

    const float* zrow0 = &zs[ty * ZS_STRIDE];
    const float* zrow1 = &zs[(ty + 32) * ZS_STRIDE];
    // ws viewed as packed pairs: element (k, 4*tx + 32*j) -> wp[k*32 + 8*j]
    const ulonglong2* wp = ((const ulonglong2*)ws) + tx;
    const ulonglong2* bp = ((const ulonglong2*)bs) + tx;

    ull acc0[8], acc1[8];

#define INIT_ACC()                                                     \
    _Pragma("unroll")                                                  \
    for (int j = 0; j < 4; j++) {                                      \
        ulonglong2 b = bp[8 * j];                                      \
        acc0[2 * j] = b.x; acc0[2 * j + 1] = b.y;                      \
        acc1[2 * j] = b.x; acc1[2 * j + 1] = b.y;                      \
    }

#define GEMM_LOOP()                                                    \
    _Pragma("unroll 8")                                                \
    for (int k2 = 0; k2 < H; k2 += 2) {                                \
        float2 a0 = *(const float2*)(zrow0 + k2);                      \
        float2 a1 = *(const float2*)(zrow1 + k2);                      \
        ull a00 = pk2(a0.x), a10 = pk2(a1.x);                          \
        ull a01 = pk2(a0.y), a11 = pk2(a1.y);                          \
        _Pragma("unroll")                                              \
        for (int j = 0; j < 4; j++) {                                  \
            ulonglong2 wA = wp[k2 * 32 + 8 * j];                       \
            fma2(acc0[2 * j],     a00, wA.x);                          \
            fma2(acc0[2 * j + 1], a00, wA.y);                          \
            fma2(acc1[2 * j],     a10, wA.x);                          \
            fma2(acc1[2 * j + 1], a10, wA.y);                          \
            ulonglong2 wB = wp[(k2 + 1) * 32 + 8 * j];                 \
            fma2(acc0[2 * j],     a01, wB.x);                          \
            fma2(acc0[2 * j + 1], a01, wB.y);                          \
            fma2(acc1[2 * j],     a11, wB.x);                          \
            fma2(acc1[2 * j + 1], a11, wB.y);                          \
        }                                                              \
    }

    // ---- GEMM 1
    INIT_ACC();
    GEMM_LOOP();
    __syncthreads();

    // ---- relu -> zs; swap in W2/b2
#pragma unroll
    for (int j = 0; j < 4; j++) {
        float2 p0 = upk(acc0[2 * j]), p1 = upk(acc0[2 * j + 1]);
        *(float4*)(&zs[ty * ZS_STRIDE + 4 * tx + 32 * j]) =
            make_float4(fmaxf(p0.x, 0.f), fmaxf(p0.y, 0.f),
                        fmaxf(p1.x, 0.f), fmaxf(p1.y, 0.f));
        float2 q0 = upk(acc1[2 * j]), q1 = upk(acc1[2 * j + 1]);
        *(float4*)(&zs[(ty + 32) * ZS_STRIDE + 4 * tx + 32 * j]) =
            make_float4(fmaxf(q0.x, 0.f), fmaxf(q0.y, 0.f),
                        fmaxf(q1.x, 0.f), fmaxf(q1.y, 0.f));
    }
#pragma unroll
    for (int i = 0; i < 16; i++)
        ((float4*)ws)[tid + i * 256] = ((const float4*)W2)[tid + i * 256];
    if (tid < 32) ((float4*)bs)[tid] = ((const float4*)b2)[tid];
    __syncthreads();

    // ---- GEMM 2
    INIT_ACC();
    GEMM_LOOP();

    // ---- store with validity re-mask
    {
        int r0g = row0 + ty;
        int r1g = row0 + ty + 32;
        float vf0 = (node_ids[r0g] >= 0) ? 1.0f : 0.0f;
        float vf1 = (node_ids[r1g] >= 0) ? 1.0f : 0.0f;
#pragma unroll
        for (int j = 0; j < 4; j++) {
            float2 p0 = upk(acc0[2 * j]), p1 = upk(acc0[2 * j + 1]);
            *(float4*)(&g_h[r0g * H + 4 * tx + 32 * j]) =
                make_float4(p0.x * vf0, p0.y * vf0, p1.x * vf0, p1.y * vf0);
            float2 q0 = upk(acc1[2 * j]), q1 = upk(acc1[2 * j + 1]);
            *(float4*)(&g_h[r1g * H + 4 * tx + 32 * j]) =
                make_float4(q0.x * vf1, q0.y * vf1, q1.x * vf1, q1.y * vf1);
        }
    }
#undef INIT_ACC
#undef GEMM_LOOP
}

__global__ void zero_out_kernel(float* __restrict__ out, int n) {
    int i = blockIdx.x * blockDim.x + threadIdx.x;
    if (i < n) out[i] = 0.0f;
}

// per-canonical-node: scatter-mean per subgraph, HT softmax weighting, add-pool per graph
__global__ void pool_kernel(const int* __restrict__ node_ids,
                            const float* __restrict__ log_probs,
                            const int* __restrict__ batch_graph,
                            const float* __restrict__ ht_alpha,
                            float* __restrict__ out) {
    __shared__ float wgt[M_SUB];
    __shared__ float cinv[M_SUB];
    __shared__ int   nid_s[M_SUB * K_SUB];
    int n = blockIdx.x;
    int tid = threadIdx.x;

    if (tid < M_SUB * K_SUB) nid_s[tid] = node_ids[n * (M_SUB * K_SUB) + tid];
    __syncthreads();

    if (tid < M_SUB) {
        int c = 0;
#pragma unroll
        for (int kk = 0; kk < K_SUB; kk++) c += (nid_s[tid * K_SUB + kk] >= 0);
        cinv[tid] = 1.0f / fmaxf((float)c, 1.0f);
    }
    if (tid == 0) {
        float alpha = ht_alpha[0];
        float v[M_SUB];
        float mx = -3.4e38f;
#pragma unroll
        for (int mm = 0; mm < M_SUB; mm++) {
            float lp = log_probs[n * M_SUB + mm];
            if (!isfinite(lp)) lp = 0.0f;
            v[mm] = -alpha * lp;
            mx = fmaxf(mx, v[mm]);
        }
        float sum = 0.0f;
#pragma unroll
        for (int mm = 0; mm < M_SUB; mm++) { v[mm] = expf(v[mm] - mx); sum += v[mm]; }
#pragma unroll
        for (int mm = 0; mm < M_SUB; mm++) wgt[mm] = v[mm] / sum;
    }
    __syncthreads();

    int d = tid;  // 128 threads = H dims
    float val = 0.0f;
#pragma unroll
    for (int mm = 0; mm < M_SUB; mm++) {
        float s = 0.0f;
#pragma unroll
        for (int kk = 0; kk < K_SUB; kk++) {
            int fi = n * (M_SUB * K_SUB) + mm * K_SUB + kk;
            if (nid_s[mm * K_SUB + kk] >= 0) s += g_h[fi * H + d];
        }
        val += wgt[mm] * s * cinv[mm];
    }
    atomicAdd(&out[batch_graph[n] * H + d], val);
}

// ---------------- launch ----------------

extern "C" void kernel_launch(void* const* d_in, const int* in_sizes, int n_in,
                              void* d_out, int out_size) {
    const int*   x_tokens    = (const int*)d_in[0];
    const int*   edge_tokens = (const int*)d_in[1];
    const int*   intra_ei    = (const int*)d_in[2];   // [2, E] row-major
    const int*   node_ids    = (const int*)d_in[3];
    // d_in[4] = valid      (bool; derived from node_ids>=0 instead)
    // d_in[5] = sub_batch  (== i/8 by construction)
    const float* log_probs   = (const float*)d_in[6];
    const int*   batch_graph = (const int*)d_in[7];
    const float* atom_emb    = (const float*)d_in[8];
    const float* bond_emb    = (const float*)d_in[9];
    const float* role_emb    = (const float*)d_in[10];
    const float* eps         = (const float*)d_in[11];
    const float* w1          = (const float*)d_in[12];
    const float* b1          = (const float*)d_in[13];
    const float* w2          = (const float*)d_in[14];
    const float* b2          = (const float*)d_in[15];
    const float* ht_alpha    = (const float*)d_in[16];
    float* out = (float*)d_out;

    const int* src = intra_ei;
    const int* dst = intra_ei + E_CNT;

    cudaFuncSetAttribute(mlp_kernel, cudaFuncAttributeMaxDynamicSharedMemorySize,
                         MLP_SMEM_BYTES);

    embed_kernel<<<(SK * 32) / 256, 256>>>(x_tokens, node_ids, atom_emb, role_emb);
    zero_aggr_kernel<<<(SK * H / 4) / 256, 256>>>();

    for (int l = 0; l < L_LAYERS; l++) {
        edge_kernel<<<(E_CNT * 32) / 256, 256>>>(src, dst, edge_tokens, bond_emb);
        mlp_kernel<<<SK / MLP_ROWS, 256, MLP_SMEM_BYTES>>>(
            w1 + l * H * H, b1 + l * H, w2 + l * H * H, b2 + l * H,
            eps, l, (l < L_LAYERS - 1) ? 1 : 0, node_ids);
    }

    zero_out_kernel<<<(NUM_G * H + 255) / 256, 256>>>(out, NUM_G * H);
    pool_kernel<<<N_TOT, H>>>(node_ids, log_probs, batch_graph, ht_alpha, out);
}

// round 5
// speedup vs baseline: 1.3392x; 1.3392x over previous
#include <cuda_runtime.h>
#include <math.h>
#include <stdint.h>

#define SK        131072
#define E_CNT     196608
#define H         128
#define N_TOT     4096
#define M_SUB     4
#define K_SUB     8
#define L_LAYERS  4
#define NUM_G     32

// ---------------- scratch (static device memory; no allocations) ----------------
__device__ float g_h[SK * H];     // node features (64 MB)
__device__ float g_aggr[SK * H];  // message aggregation buffer (64 MB)
__device__ float g_mid[SK * H];   // relu intermediate between the two GEMMs (64 MB)

// ---------------- 3xTF32 helpers ----------------
// exact split: hi = truncate-to-tf32(z) (top 10 mantissa bits, exact), lo = z - hi
__device__ __forceinline__ void split_tf32(float z, uint32_t& hi, uint32_t& lo) {
    uint32_t zb = __float_as_uint(z);
    hi = zb & 0xFFFFE000u;
    lo = __float_as_uint(z - __uint_as_float(hi));
}

__device__ __forceinline__ void mma_tf32(float* c,
                                         uint32_t a0, uint32_t a1, uint32_t a2, uint32_t a3,
                                         uint32_t b0, uint32_t b1) {
    asm volatile(
        "mma.sync.aligned.m16n8k8.row.col.f32.tf32.tf32.f32 "
        "{%0,%1,%2,%3}, {%4,%5,%6,%7}, {%8,%9}, {%0,%1,%2,%3};"
        : "+f"(c[0]), "+f"(c[1]), "+f"(c[2]), "+f"(c[3])
        : "r"(a0), "r"(a1), "r"(a2), "r"(a3), "r"(b0), "r"(b1));
}

// ================= small kernels =================
__global__ void zero_aggr_kernel() {
    int i = blockIdx.x * blockDim.x + threadIdx.x;
    ((float4*)g_aggr)[i] = make_float4(0.f, 0.f, 0.f, 0.f);
}

__global__ void embed_kernel(const int* __restrict__ x_tokens,
                             const int* __restrict__ node_ids,
                             const float* __restrict__ atom_emb,
                             const float* __restrict__ role_emb) {
    int t = blockIdx.x * blockDim.x + threadIdx.x;
    int node = t >> 5;
    int lane = t & 31;
    int tok = x_tokens[node];
    float vf = (node_ids[node] >= 0) ? 1.0f : 0.0f;
    int is_root = ((node & (K_SUB - 1)) == 0) ? 1 : 0;
    int c = lane * 4;
    float4 a = *(const float4*)(&atom_emb[tok * H + c]);
    float4 r = *(const float4*)(&role_emb[is_root * H + c]);
    float4 o;
    o.x = (a.x + r.x) * vf; o.y = (a.y + r.y) * vf;
    o.z = (a.z + r.z) * vf; o.w = (a.w + r.w) * vf;
    *(float4*)(&g_h[node * H + c]) = o;
}

__global__ void edge_kernel(const int* __restrict__ src,
                            const int* __restrict__ dst,
                            const int* __restrict__ etok,
                            const float* __restrict__ bond_emb) {
    int t = blockIdx.x * blockDim.x + threadIdx.x;
    int e = t >> 5;
    if (e >= E_CNT) return;
    int lane = t & 31;
    int s = src[e], d = dst[e], bt = etok[e];
    int c = lane * 4;
    float4 hv = *(const float4*)(&g_h[s * H + c]);
    float4 bv = *(const float4*)(&bond_emb[bt * H + c]);
    float4 m;
    m.x = fmaxf(hv.x + bv.x, 0.f); m.y = fmaxf(hv.y + bv.y, 0.f);
    m.z = fmaxf(hv.z + bv.z, 0.f); m.w = fmaxf(hv.w + bv.w, 0.f);
    float* zp = &g_aggr[d * H + c];
    atomicAdd(zp + 0, m.x); atomicAdd(zp + 1, m.y);
    atomicAdd(zp + 2, m.z); atomicAdd(zp + 3, m.w);
}

// ================= 3xTF32 mma.sync GEMM =================
// MODE 1: Z=(1+eps)*h+aggr ; out = relu(Z@W1+b1) -> g_mid     (optionally zero aggr)
// MODE 2: Z=g_mid          ; out = (Z@W2+b2)*vf  -> g_h
//
// Persistent blocks (2/SM). Block = 256 threads = 8 warps (4 row-groups x 2 col-groups).
// Block tile: 64 rows x 128 cols. Warp tile: 16 rows x 64 cols.
// W is staged once per kernel as W^T [n][k] (stride 132 -> conflict-free frags).
#define TILE_R  64
#define NTILES  (SK / TILE_R)             // 2048
#define ZSTR    132
#define WS_OFF  (TILE_R * ZSTR)           // 8448
#define B_OFF   (WS_OFF + H * ZSTR)       // 25344
#define SMEMF   (B_OFF + H)               // 25472 floats
#define SMEMB   (SMEMF * 4)               // 101888 bytes
#define GRID_G  296

template <int MODE>
__global__ __launch_bounds__(256, 2)
void gemm_kernel(const float* __restrict__ W, const float* __restrict__ bias,
                 const float* __restrict__ eps, int l, int zero_next,
                 const int* __restrict__ node_ids) {
    extern __shared__ float sm[];
    float* zs = sm;             // [64][132]
    float* ws = sm + WS_OFF;    // W^T [128][132]
    float* bs = sm + B_OFF;     // [128]

    const int tid  = threadIdx.x;
    const int w    = tid >> 5;
    const int lane = tid & 31;
    const int gid  = lane >> 2;        // 0..7
    const int tig  = lane & 3;         // 0..3
    const int wr   = (w & 3) * 16;     // warp row offset in tile
    const int wc   = (w >> 2) * 64;    // warp col offset

    // ---- stage W^T (once per kernel; conflicts here are amortized away)
#pragma unroll
    for (int i = 0; i < 16; i++) {
        int idx4 = tid + i * 256;
        int k  = idx4 >> 5;
        int n0 = (idx4 & 31) << 2;
        float4 w4 = ((const float4*)W)[idx4];
        ws[(n0 + 0) * ZSTR + k] = w4.x;
        ws[(n0 + 1) * ZSTR + k] = w4.y;
        ws[(n0 + 2) * ZSTR + k] = w4.z;
        ws[(n0 + 3) * ZSTR + k] = w4.w;
    }
    if (tid < 32) ((float4*)bs)[tid] = ((const float4*)bias)[tid];
    const float epsl = (MODE == 1) ? (1.0f + eps[l]) : 0.0f;
    __syncthreads();

    for (int t = blockIdx.x; t < NTILES; t += gridDim.x) {
        const int row0 = t * TILE_R;

        // ---- stage Z tile (coalesced float4)
#pragma unroll
        for (int i = 0; i < 8; i++) {
            int idx4 = tid + i * 256;
            int r = idx4 >> 5;
            int c = (idx4 & 31) << 2;
            float4 z4;
            if (MODE == 1) {
                float4 h4 = *(const float4*)&g_h[(row0 + r) * H + c];
                float4 a4 = *(const float4*)&g_aggr[(row0 + r) * H + c];
                z4.x = epsl * h4.x + a4.x; z4.y = epsl * h4.y + a4.y;
                z4.z = epsl * h4.z + a4.z; z4.w = epsl * h4.w + a4.w;
                if (zero_next)
                    *(float4*)&g_aggr[(row0 + r) * H + c] = make_float4(0.f, 0.f, 0.f, 0.f);
            } else {
                z4 = *(const float4*)&g_mid[(row0 + r) * H + c];
            }
            *(float4*)&zs[r * ZSTR + c] = z4;
        }
        __syncthreads();

        // ---- accumulators init with bias (cols n = wc + 8i + 2*tig, +1)
        float acc[8][4];
#pragma unroll
        for (int i = 0; i < 8; i++) {
            float b0 = bs[wc + 8 * i + 2 * tig];
            float b1 = bs[wc + 8 * i + 2 * tig + 1];
            acc[i][0] = b0; acc[i][1] = b1;
            acc[i][2] = b0; acc[i][3] = b1;
        }

        // ---- 3xTF32 K loop (split in registers)
        const float* za = &zs[(wr + gid) * ZSTR + tig];
#pragma unroll 2
        for (int k0 = 0; k0 < H; k0 += 8) {
            uint32_t ah[4], al[4];
            split_tf32(za[k0],                 ah[0], al[0]);   // (gid,   tig)
            split_tf32(za[8 * ZSTR + k0],      ah[1], al[1]);   // (gid+8, tig)
            split_tf32(za[k0 + 4],             ah[2], al[2]);   // (gid,   tig+4)
            split_tf32(za[8 * ZSTR + k0 + 4],  ah[3], al[3]);   // (gid+8, tig+4)
#pragma unroll
            for (int i = 0; i < 8; i++) {
                const float* wn = &ws[(wc + 8 * i + gid) * ZSTR + k0 + tig];
                uint32_t bh0, bl0, bh1, bl1;
                split_tf32(wn[0], bh0, bl0);
                split_tf32(wn[4], bh1, bl1);
                mma_tf32(acc[i], ah[0], ah[1], ah[2], ah[3], bh0, bh1);
                mma_tf32(acc[i], al[0], al[1], al[2], al[3], bh0, bh1);
                mma_tf32(acc[i], ah[0], ah[1], ah[2], ah[3], bl0, bl1);
            }
        }

        // ---- epilogue straight to global (rows wr+gid, wr+gid+8)
        float* dstb = (MODE == 1) ? g_mid : g_h;
        const int r0g = row0 + wr + gid;
        const int r1g = r0g + 8;
        float vf0 = 1.0f, vf1 = 1.0f;
        if (MODE == 2) {
            vf0 = (node_ids[r0g] >= 0) ? 1.0f : 0.0f;
            vf1 = (node_ids[r1g] >= 0) ? 1.0f : 0.0f;
        }
#pragma unroll
        for (int i = 0; i < 8; i++) {
            int n = wc + 8 * i + 2 * tig;
            float2 v0, v1;
            if (MODE == 1) {
                v0 = make_float2(fmaxf(acc[i][0], 0.f), fmaxf(acc[i][1], 0.f));
                v1 = make_float2(fmaxf(acc[i][2], 0.f), fmaxf(acc[i][3], 0.f));
            } else {
                v0 = make_float2(acc[i][0] * vf0, acc[i][1] * vf0);
                v1 = make_float2(acc[i][2] * vf1, acc[i][3] * vf1);
            }
            *(float2*)&dstb[r0g * H + n] = v0;
            *(float2*)&dstb[r1g * H + n] = v1;
        }
        __syncthreads();   // protect zs before next tile's staging
    }
}

// ================= pooling =================
__global__ void zero_out_kernel(float* __restrict__ out, int n) {
    int i = blockIdx.x * blockDim.x + threadIdx.x;
    if (i < n) out[i] = 0.0f;
}

__global__ void pool_kernel(const int* __restrict__ node_ids,
                            const float* __restrict__ log_probs,
                            const int* __restrict__ batch_graph,
                            const float* __restrict__ ht_alpha,
                            float* __restrict__ out) {
    __shared__ float wgt[M_SUB];
    __shared__ float cinv[M_SUB];
    __shared__ int   nid_s[M_SUB * K_SUB];
    int n = blockIdx.x;
    int tid = threadIdx.x;

    if (tid < M_SUB * K_SUB) nid_s[tid] = node_ids[n * (M_SUB * K_SUB) + tid];
    __syncthreads();

    if (tid < M_SUB) {
        int c = 0;
#pragma unroll
        for (int kk = 0; kk < K_SUB; kk++) c += (nid_s[tid * K_SUB + kk] >= 0);
        cinv[tid] = 1.0f / fmaxf((float)c, 1.0f);
    }
    if (tid == 0) {
        float alpha = ht_alpha[0];
        float v[M_SUB];
        float mx = -3.4e38f;
#pragma unroll
        for (int mm = 0; mm < M_SUB; mm++) {
            float lp = log_probs[n * M_SUB + mm];
            if (!isfinite(lp)) lp = 0.0f;
            v[mm] = -alpha * lp;
            mx = fmaxf(mx, v[mm]);
        }
        float sum = 0.0f;
#pragma unroll
        for (int mm = 0; mm < M_SUB; mm++) { v[mm] = expf(v[mm] - mx); sum += v[mm]; }
#pragma unroll
        for (int mm = 0; mm < M_SUB; mm++) wgt[mm] = v[mm] / sum;
    }
    __syncthreads();

    int d = tid;
    float val = 0.0f;
#pragma unroll
    for (int mm = 0; mm < M_SUB; mm++) {
        float s = 0.0f;
#pragma unroll
        for (int kk = 0; kk < K_SUB; kk++) {
            int fi = n * (M_SUB * K_SUB) + mm * K_SUB + kk;
            if (nid_s[mm * K_SUB + kk] >= 0) s += g_h[fi * H + d];
        }
        val += wgt[mm] * s * cinv[mm];
    }
    atomicAdd(&out[batch_graph[n] * H + d], val);
}

// ================= launch =================
extern "C" void kernel_launch(void* const* d_in, const int* in_sizes, int n_in,
                              void* d_out, int out_size) {
    const int*   x_tokens    = (const int*)d_in[0];
    const int*   edge_tokens = (const int*)d_in[1];
    const int*   intra_ei    = (const int*)d_in[2];
    const int*   node_ids    = (const int*)d_in[3];
    const float* log_probs   = (const float*)d_in[6];
    const int*   batch_graph = (const int*)d_in[7];
    const float* atom_emb    = (const float*)d_in[8];
    const float* bond_emb    = (const float*)d_in[9];
    const float* role_emb    = (const float*)d_in[10];
    const float* eps         = (const float*)d_in[11];
    const float* w1          = (const float*)d_in[12];
    const float* b1          = (const float*)d_in[13];
    const float* w2          = (const float*)d_in[14];
    const float* b2          = (const float*)d_in[15];
    const float* ht_alpha    = (const float*)d_in[16];
    float* out = (float*)d_out;

    const int* src = intra_ei;
    const int* dst = intra_ei + E_CNT;

    cudaFuncSetAttribute(gemm_kernel<1>, cudaFuncAttributeMaxDynamicSharedMemorySize, SMEMB);
    cudaFuncSetAttribute(gemm_kernel<2>, cudaFuncAttributeMaxDynamicSharedMemorySize, SMEMB);

    embed_kernel<<<(SK * 32) / 256, 256>>>(x_tokens, node_ids, atom_emb, role_emb);
    zero_aggr_kernel<<<(SK * H / 4) / 256, 256>>>();

    for (int l = 0; l < L_LAYERS; l++) {
        edge_kernel<<<(E_CNT * 32) / 256, 256>>>(src, dst, edge_tokens, bond_emb);
        gemm_kernel<1><<<GRID_G, 256, SMEMB>>>(
            w1 + l * H * H, b1 + l * H, eps, l, (l < L_LAYERS - 1) ? 1 : 0, node_ids);
        gemm_kernel<2><<<GRID_G, 256, SMEMB>>>(
            w2 + l * H * H, b2 + l * H, (const float*)0, 0, 0, node_ids);
    }

    zero_out_kernel<<<(NUM_G * H + 255) / 256, 256>>>(out, NUM_G * H);
    pool_kernel<<<N_TOT, H>>>(node_ids, log_probs, batch_graph, ht_alpha, out);
}

// round 6
// speedup vs baseline: 1.3559x; 1.0125x over previous
#include <cuda_runtime.h>
#include <math.h>
#include <stdint.h>

#define SK        131072
#define E_CNT     196608
#define H         128
#define N_TOT     4096
#define M_SUB     4
#define K_SUB     8
#define L_LAYERS  4
#define NUM_G     32

// ---------------- scratch (static device memory; no allocations) ----------------
__device__ float g_h[SK * H];     // node features (64 MB)
__device__ float g_aggr[SK * H];  // message aggregation buffer (64 MB)
__device__ float g_mid[SK * H];   // relu intermediate between the two GEMMs (64 MB)

// ---------------- 3xTF32 helpers ----------------
__device__ __forceinline__ void split_tf32(float z, uint32_t& hi, uint32_t& lo) {
    uint32_t zb = __float_as_uint(z);
    hi = zb & 0xFFFFE000u;
    lo = __float_as_uint(z - __uint_as_float(hi));
}

__device__ __forceinline__ void mma_tf32(float* c,
                                         uint32_t a0, uint32_t a1, uint32_t a2, uint32_t a3,
                                         uint32_t b0, uint32_t b1) {
    asm volatile(
        "mma.sync.aligned.m16n8k8.row.col.f32.tf32.tf32.f32 "
        "{%0,%1,%2,%3}, {%4,%5,%6,%7}, {%8,%9}, {%0,%1,%2,%3};"
        : "+f"(c[0]), "+f"(c[1]), "+f"(c[2]), "+f"(c[3])
        : "r"(a0), "r"(a1), "r"(a2), "r"(a3), "r"(b0), "r"(b1));
}

// ================= small kernels =================
__global__ void zero_aggr_kernel() {
    int i = blockIdx.x * blockDim.x + threadIdx.x;
    ((float4*)g_aggr)[i] = make_float4(0.f, 0.f, 0.f, 0.f);
}

__global__ void embed_kernel(const int* __restrict__ x_tokens,
                             const int* __restrict__ node_ids,
                             const float* __restrict__ atom_emb,
                             const float* __restrict__ role_emb) {
    int t = blockIdx.x * blockDim.x + threadIdx.x;
    int node = t >> 5;
    int lane = t & 31;
    int tok = x_tokens[node];
    float vf = (node_ids[node] >= 0) ? 1.0f : 0.0f;
    int is_root = ((node & (K_SUB - 1)) == 0) ? 1 : 0;
    int c = lane * 4;
    float4 a = *(const float4*)(&atom_emb[tok * H + c]);
    float4 r = *(const float4*)(&role_emb[is_root * H + c]);
    float4 o;
    o.x = (a.x + r.x) * vf; o.y = (a.y + r.y) * vf;
    o.z = (a.z + r.z) * vf; o.w = (a.w + r.w) * vf;
    *(float4*)(&g_h[node * H + c]) = o;
}

__global__ void edge_kernel(const int* __restrict__ src,
                            const int* __restrict__ dst,
                            const int* __restrict__ etok,
                            const float* __restrict__ bond_emb) {
    int t = blockIdx.x * blockDim.x + threadIdx.x;
    int e = t >> 5;
    if (e >= E_CNT) return;
    int lane = t & 31;
    int s = src[e], d = dst[e], bt = etok[e];
    int c = lane * 4;
    float4 hv = *(const float4*)(&g_h[s * H + c]);
    float4 bv = *(const float4*)(&bond_emb[bt * H + c]);
    float4 m;
    m.x = fmaxf(hv.x + bv.x, 0.f); m.y = fmaxf(hv.y + bv.y, 0.f);
    m.z = fmaxf(hv.z + bv.z, 0.f); m.w = fmaxf(hv.w + bv.w, 0.f);
    float* zp = &g_aggr[d * H + c];
    asm volatile("red.global.add.v4.f32 [%0], {%1, %2, %3, %4};"
                 :: "l"(zp), "f"(m.x), "f"(m.y), "f"(m.z), "f"(m.w) : "memory");
}

// ================= 3xTF32 mma.sync GEMM =================
// MODE 1: Z=(1+eps)*h+aggr ; out = relu(Z@W1+b1) -> g_mid     (optionally zero aggr)
// MODE 2: Z=g_mid          ; out = (Z@W2+b2)*vf  -> g_h
//
// Persistent (grid=148, 1 block/SM). Block = 256 threads = 8 warps
// (4 row-groups x 2 col-groups). Block tile 128x128, warp tile 32x64.
// W pre-split once per kernel into smem (hi,lo) float2 pairs, W^T layout
// [n][k] with float2-stride 132 (132 mod 16 = 4 -> conflict-free LDS.64).
#define TILE_R  128
#define NTILES  (SK / TILE_R)               // 1024
#define ZSTR    132
#define WPSTR   132
#define ZS_FLOATS (TILE_R * ZSTR)           // 16896
#define SMEMB   (ZS_FLOATS * 4 + H * WPSTR * 8)   // 67584 + 135168 = 202752
#define GRID_G  148

template <int MODE>
__global__ __launch_bounds__(256, 1)
void gemm_kernel(const float* __restrict__ W, const float* __restrict__ bias,
                 const float* __restrict__ eps, int l, int zero_next,
                 const int* __restrict__ node_ids) {
    extern __shared__ float sm[];
    float*  zs = sm;                           // [128][132] floats
    float2* wp = (float2*)(sm + ZS_FLOATS);    // [128][132] (hi,lo) pairs

    const int tid  = threadIdx.x;
    const int w    = tid >> 5;
    const int lane = tid & 31;
    const int gid  = lane >> 2;        // 0..7
    const int tig  = lane & 3;         // 0..3
    const int wr   = (w & 3) * 32;     // warp row offset (0/32/64/96)
    const int wc   = (w >> 2) * 64;    // warp col offset (0/64)

    // ---- stage W^T pre-split into (hi,lo) pairs (once per kernel)
#pragma unroll
    for (int i = 0; i < 16; i++) {
        int idx4 = tid + i * 256;
        int k  = idx4 >> 5;
        int n0 = (idx4 & 31) << 2;
        float4 w4 = ((const float4*)W)[idx4];
        float wv[4] = {w4.x, w4.y, w4.z, w4.w};
#pragma unroll
        for (int j = 0; j < 4; j++) {
            uint32_t hb, lb;
            split_tf32(wv[j], hb, lb);
            wp[(n0 + j) * WPSTR + k] =
                make_float2(__uint_as_float(hb), __uint_as_float(lb));
        }
    }

    // ---- bias for this thread's 16 columns, in registers
    float bcol[16];
#pragma unroll
    for (int i = 0; i < 8; i++) {
        float2 b2 = *(const float2*)&bias[wc + 8 * i + 2 * tig];
        bcol[2 * i] = b2.x; bcol[2 * i + 1] = b2.y;
    }
    const float epsl = (MODE == 1) ? (1.0f + eps[l]) : 0.0f;
    __syncthreads();

    for (int t = blockIdx.x; t < NTILES; t += gridDim.x) {
        const int row0 = t * TILE_R;

        // ---- stage Z tile (coalesced float4; 4096 float4s)
#pragma unroll
        for (int i = 0; i < 16; i++) {
            int idx4 = tid + i * 256;
            int r = idx4 >> 5;
            int c = (idx4 & 31) << 2;
            float4 z4;
            if (MODE == 1) {
                float4 h4 = *(const float4*)&g_h[(row0 + r) * H + c];
                float4 a4 = *(const float4*)&g_aggr[(row0 + r) * H + c];
                z4.x = epsl * h4.x + a4.x; z4.y = epsl * h4.y + a4.y;
                z4.z = epsl * h4.z + a4.z; z4.w = epsl * h4.w + a4.w;
                if (zero_next)
                    *(float4*)&g_aggr[(row0 + r) * H + c] = make_float4(0.f, 0.f, 0.f, 0.f);
            } else {
                z4 = *(const float4*)&g_mid[(row0 + r) * H + c];
            }
            *(float4*)&zs[r * ZSTR + c] = z4;
        }
        __syncthreads();

        // ---- accumulators (2 m-frags x 8 n-frags x 4)
        float acc[2][8][4];
#pragma unroll
        for (int m = 0; m < 2; m++)
#pragma unroll
            for (int i = 0; i < 8; i++) {
                acc[m][i][0] = bcol[2 * i];     acc[m][i][1] = bcol[2 * i + 1];
                acc[m][i][2] = bcol[2 * i];     acc[m][i][3] = bcol[2 * i + 1];
            }

        // ---- 3xTF32 K loop (A split in regs, W pre-split in smem)
        const float* za = &zs[(wr + gid) * ZSTR + tig];
#pragma unroll 2
        for (int k0 = 0; k0 < H; k0 += 8) {
            uint32_t ah[2][4], al[2][4];
#pragma unroll
            for (int m = 0; m < 2; m++) {
                const float* zm = za + m * 16 * ZSTR;
                split_tf32(zm[k0],                ah[m][0], al[m][0]);
                split_tf32(zm[8 * ZSTR + k0],     ah[m][1], al[m][1]);
                split_tf32(zm[k0 + 4],            ah[m][2], al[m][2]);
                split_tf32(zm[8 * ZSTR + k0 + 4], ah[m][3], al[m][3]);
            }
#pragma unroll
            for (int i = 0; i < 8; i++) {
                const float2* wq = &wp[(wc + 8 * i + gid) * WPSTR + k0 + tig];
                float2 p0 = wq[0];   // (hi,lo) at k = k0+tig
                float2 p1 = wq[4];   // (hi,lo) at k = k0+tig+4
                uint32_t bh0 = __float_as_uint(p0.x), bl0 = __float_as_uint(p0.y);
                uint32_t bh1 = __float_as_uint(p1.x), bl1 = __float_as_uint(p1.y);
#pragma unroll
                for (int m = 0; m < 2; m++) {
                    mma_tf32(acc[m][i], ah[m][0], ah[m][1], ah[m][2], ah[m][3], bh0, bh1);
                    mma_tf32(acc[m][i], al[m][0], al[m][1], al[m][2], al[m][3], bh0, bh1);
                    mma_tf32(acc[m][i], ah[m][0], ah[m][1], ah[m][2], ah[m][3], bl0, bl1);
                }
            }
        }

        // ---- epilogue straight to global
        float* dstb = (MODE == 1) ? g_mid : g_h;
#pragma unroll
        for (int m = 0; m < 2; m++) {
            const int r0g = row0 + wr + m * 16 + gid;
            const int r1g = r0g + 8;
            float vf0 = 1.0f, vf1 = 1.0f;
            if (MODE == 2) {
                vf0 = (node_ids[r0g] >= 0) ? 1.0f : 0.0f;
                vf1 = (node_ids[r1g] >= 0) ? 1.0f : 0.0f;
            }
#pragma unroll
            for (int i = 0; i < 8; i++) {
                int n = wc + 8 * i + 2 * tig;
                float2 v0, v1;
                if (MODE == 1) {
                    v0 = make_float2(fmaxf(acc[m][i][0], 0.f), fmaxf(acc[m][i][1], 0.f));
                    v1 = make_float2(fmaxf(acc[m][i][2], 0.f), fmaxf(acc[m][i][3], 0.f));
                } else {
                    v0 = make_float2(acc[m][i][0] * vf0, acc[m][i][1] * vf0);
                    v1 = make_float2(acc[m][i][2] * vf1, acc[m][i][3] * vf1);
                }
                *(float2*)&dstb[r0g * H + n] = v0;
                *(float2*)&dstb[r1g * H + n] = v1;
            }
        }
        __syncthreads();   // protect zs before next tile's staging
    }
}

// ================= pooling =================
__global__ void zero_out_kernel(float* __restrict__ out, int n) {
    int i = blockIdx.x * blockDim.x + threadIdx.x;
    if (i < n) out[i] = 0.0f;
}

__global__ void pool_kernel(const int* __restrict__ node_ids,
                            const float* __restrict__ log_probs,
                            const int* __restrict__ batch_graph,
                            const float* __restrict__ ht_alpha,
                            float* __restrict__ out) {
    __shared__ float wgt[M_SUB];
    __shared__ float cinv[M_SUB];
    __shared__ int   nid_s[M_SUB * K_SUB];
    int n = blockIdx.x;
    int tid = threadIdx.x;

    if (tid < M_SUB * K_SUB) nid_s[tid] = node_ids[n * (M_SUB * K_SUB) + tid];
    __syncthreads();

    if (tid < M_SUB) {
        int c = 0;
#pragma unroll
        for (int kk = 0; kk < K_SUB; kk++) c += (nid_s[tid * K_SUB + kk] >= 0);
        cinv[tid] = 1.0f / fmaxf((float)c, 1.0f);
    }
    if (tid == 0) {
        float alpha = ht_alpha[0];
        float v[M_SUB];
        float mx = -3.4e38f;
#pragma unroll
        for (int mm = 0; mm < M_SUB; mm++) {
            float lp = log_probs[n * M_SUB + mm];
            if (!isfinite(lp)) lp = 0.0f;
            v[mm] = -alpha * lp;
            mx = fmaxf(mx, v[mm]);
        }
        float sum = 0.0f;
#pragma unroll
        for (int mm = 0; mm < M_SUB; mm++) { v[mm] = expf(v[mm] - mx); sum += v[mm]; }
#pragma unroll
        for (int mm = 0; mm < M_SUB; mm++) wgt[mm] = v[mm] / sum;
    }
    __syncthreads();

    int d = tid;
    float val = 0.0f;
#pragma unroll
    for (int mm = 0; mm < M_SUB; mm++) {
        float s = 0.0f;
#pragma unroll
        for (int kk = 0; kk < K_SUB; kk++) {
            int fi = n * (M_SUB * K_SUB) + mm * K_SUB + kk;
            if (nid_s[mm * K_SUB + kk] >= 0) s += g_h[fi * H + d];
        }
        val += wgt[mm] * s * cinv[mm];
    }
    atomicAdd(&out[batch_graph[n] * H + d], val);
}

// ================= launch =================
extern "C" void kernel_launch(void* const* d_in, const int* in_sizes, int n_in,
                              void* d_out, int out_size) {
    const int*   x_tokens    = (const int*)d_in[0];
    const int*   edge_tokens = (const int*)d_in[1];
    const int*   intra_ei    = (const int*)d_in[2];
    const int*   node_ids    = (const int*)d_in[3];
    const float* log_probs   = (const float*)d_in[6];
    const int*   batch_graph = (const int*)d_in[7];
    const float* atom_emb    = (const float*)d_in[8];
    const float* bond_emb    = (const float*)d_in[9];
    const float* role_emb    = (const float*)d_in[10];
    const float* eps         = (const float*)d_in[11];
    const float* w1          = (const float*)d_in[12];
    const float* b1          = (const float*)d_in[13];
    const float* w2          = (const float*)d_in[14];
    const float* b2          = (const float*)d_in[15];
    const float* ht_alpha    = (const float*)d_in[16];
    float* out = (float*)d_out;

    const int* src = intra_ei;
    const int* dst = intra_ei + E_CNT;

    cudaFuncSetAttribute(gemm_kernel<1>, cudaFuncAttributeMaxDynamicSharedMemorySize, SMEMB);
    cudaFuncSetAttribute(gemm_kernel<2>, cudaFuncAttributeMaxDynamicSharedMemorySize, SMEMB);

    embed_kernel<<<(SK * 32) / 256, 256>>>(x_tokens, node_ids, atom_emb, role_emb);
    zero_aggr_kernel<<<(SK * H / 4) / 256, 256>>>();

    for (int l = 0; l < L_LAYERS; l++) {
        edge_kernel<<<(E_CNT * 32) / 256, 256>>>(src, dst, edge_tokens, bond_emb);
        gemm_kernel<1><<<GRID_G, 256, SMEMB>>>(
            w1 + l * H * H, b1 + l * H, eps, l, (l < L_LAYERS - 1) ? 1 : 0, node_ids);
        gemm_kernel<2><<<GRID_G, 256, SMEMB>>>(
            w2 + l * H * H, b2 + l * H, (const float*)0, 0, 0, node_ids);
    }

    zero_out_kernel<<<(NUM_G * H + 255) / 256, 256>>>(out, NUM_G * H);
    pool_kernel<<<N_TOT, H>>>(node_ids, log_probs, batch_graph, ht_alpha, out);
}